// round 8
// baseline (speedup 1.0000x reference)
#include <cuda_runtime.h>
#include <math.h>

#define L       16384
#define NMODES  64
#define THREADS 512
#define SW(a) ((a) ^ (((a) >> 4) & 15))

__device__ float2 g_Hc[L];   // H[k]/L at position: block c=k0*16+k1, then q1*16+q0
__device__ float2 g_twA[1024];  // e^{-i pi t/8192}
__device__ float2 g_twB[64];    // e^{-i pi s/512}
__device__ float2 g_twM[4];     // e^{-i pi s/32}

// ---------------------------------------------------------------------------
union F2U { float2 f; unsigned long long u; };

__device__ __forceinline__ float2 f2add(float2 a, float2 b) {
    F2U x, y, r; x.f = a; y.f = b;
    asm("add.rn.f32x2 %0, %1, %2;" : "=l"(r.u) : "l"(x.u), "l"(y.u));
    return r.f;
}
__device__ __forceinline__ float2 f2fma(float2 a, float2 b, float2 c) {
    F2U x, y, z, r; x.f = a; y.f = b; z.f = c;
    asm("fma.rn.f32x2 %0, %1, %2, %3;" : "=l"(r.u) : "l"(x.u), "l"(y.u), "l"(z.u));
    return r.f;
}
__device__ __forceinline__ float2 f2sub(float2 a, float2 b) {
    return f2fma(b, make_float2(-1.0f, -1.0f), a);
}
__device__ __forceinline__ float2 cmulf(float2 a, float2 b) {     // a*b
    return make_float2(a.x*b.x - a.y*b.y, a.x*b.y + a.y*b.x);
}
__device__ __forceinline__ float2 cmulcf(float2 a, float2 b) {    // a*conj(b)
    return make_float2(a.x*b.x + a.y*b.y, a.y*b.x - a.x*b.y);
}
__device__ __forceinline__ float2 f2shfl_xor(float2 v, int m) {
    float2 r;
    r.x = __shfl_xor_sync(0xFFFFFFFFu, v.x, m);
    r.y = __shfl_xor_sync(0xFFFFFFFFu, v.y, m);
    return r;
}

// digit-swap permutation of dft16 outputs (involution)
__host__ __device__ constexpr int sigc(int u) { return 4 * (u & 3) + (u >> 2); }

// position of frequency k: k = k0 + 16k1 + 256q0 + 4096q1 (q = q0+16q1 = 64-DFT freq)
// pos = k0*1024 + k1*64 + q1*16 + q0
__device__ __forceinline__ int scramble(int k) {
    return ((k & 15) << 10) | (((k >> 4) & 15) << 6)
         | (((k >> 12) & 3) << 4) | ((k >> 8) & 15);
}

// ---------------------------------------------------------------------------
// Precompute: twiddle tables + g_Hc[scramble(k)] = H[k]/L
// ---------------------------------------------------------------------------
__global__ void k_hc(const float* __restrict__ Lr, const float* __restrict__ Li,
                     const float* __restrict__ wr, const float* __restrict__ wi,
                     const float* __restrict__ dtp) {
    __shared__ float4 md[NMODES];
    int t = threadIdx.x;
    int gid = blockIdx.x * blockDim.x + t;
    if (gid < 1024) {
        float2 v;
        sincospif(-(float)gid / 8192.0f, &v.y, &v.x);
        g_twA[gid] = v;
        if (gid < 64) {
            sincospif(-(float)gid / 512.0f, &v.y, &v.x);
            g_twB[gid] = v;
        }
        if (gid < 4) {
            sincospif(-(float)gid / 32.0f, &v.y, &v.x);
            g_twM[gid] = v;
        }
    }
    if (t < NMODES) {
        int n = t;
        float dt = dtp[0];
        float lr = Lr[n], li = Li[n];
        float zr = dt * lr, zi = dt * li;
        float er = expf(zr);
        float sz, cz; sincosf(zi, &sz, &cz);
        float rr = er * cz, ri = er * sz;
        float rLm = expf(zr * (float)L);
        float Er = 1.0f, Ei = 0.0f;
        if (rLm > 1e-35f) {
            float sa, ca; sincosf(zi * (float)L, &sa, &ca);
            Er = 1.0f - rLm * ca; Ei = -rLm * sa;
        }
        float emr = rr - 1.0f, emi = ri;
        float il2 = 1.0f / (lr*lr + li*li);
        float qr = (emr*lr + emi*li) * il2;
        float qi = (emi*lr - emr*li) * il2;
        float Cr = wr[n]*qr - wi[n]*qi;
        float Ci = wr[n]*qi + wi[n]*qr;
        md[n] = make_float4(rr, ri, Cr*Er - Ci*Ei, Cr*Ei + Ci*Er);
    }
    __syncthreads();
    int kp = gid;
    if (kp > L / 2) return;
    float s, c;
    sincospif(2.0f * (float)kp / (float)L, &s, &c);
    float px = 0.f, py = 0.f, mx = 0.f, my = 0.f;
#pragma unroll 4
    for (int n = 0; n < NMODES; n++) {
        float4 m = md[n];
        float rc = m.x * c, rs = m.y * s;
        float rrs = m.x * s, ric = m.y * c;
        float dr = 1.0f - (rc + rs);
        float di = rrs - ric;
        float inv = 1.0f / (dr*dr + di*di);
        px += (m.z*dr + m.w*di) * inv;
        py += (m.w*dr - m.z*di) * inv;
        float dr2 = 1.0f - (rc - rs);
        float di2 = -rrs - ric;
        float inv2 = 1.0f / (dr2*dr2 + di2*di2);
        mx += (m.z*dr2 + m.w*di2) * inv2;
        my += (m.w*dr2 - m.z*di2) * inv2;
    }
    const float sc = 1.0f / (2.0f * (float)L);
    g_Hc[scramble(kp)]               = make_float2((px + mx) * sc, (py - my) * sc);
    g_Hc[scramble((L - kp) & (L-1))] = make_float2((px + mx) * sc, (my - py) * sc);
}

// ---------------------------------------------------------------------------
// Butterflies
// ---------------------------------------------------------------------------
template<bool INV>
__device__ __forceinline__ void dft4(float2& a, float2& b, float2& c, float2& d) {
    float2 t0 = f2add(a, c);
    float2 t1 = f2sub(a, c);
    float2 t2 = f2add(b, d);
    float2 t3 = f2sub(b, d);
    a = f2add(t0, t2);
    c = f2sub(t0, t2);
    float2 t3r = INV ? make_float2(-t3.y, t3.x) : make_float2(t3.y, -t3.x);
    b = f2add(t1, t3r);
    d = f2sub(t1, t3r);
}

// In-place DFT-16 (conj when INV). Digit u's output lands at slot sigc(u).
template<bool INV>
__device__ __forceinline__ void dft16(float2* a) {
    const float C1 = 0.92387953251128675613f;
    const float S1 = 0.38268343236508977173f;
    const float HS = 0.70710678118654752440f;
    const float sg = INV ? 1.0f : -1.0f;
    dft4<INV>(a[0], a[4], a[8],  a[12]);
    dft4<INV>(a[1], a[5], a[9],  a[13]);
    dft4<INV>(a[2], a[6], a[10], a[14]);
    dft4<INV>(a[3], a[7], a[11], a[15]);
    const float2 W1 = make_float2( C1, sg*S1);
    const float2 W2 = make_float2( HS, sg*HS);
    const float2 W3 = make_float2( S1, sg*C1);
    const float2 W6 = make_float2(-HS, sg*HS);
    const float2 W9 = make_float2(-C1, -sg*S1);
    a[5]  = cmulf(a[5],  W1);
    a[6]  = cmulf(a[6],  W2);
    a[7]  = cmulf(a[7],  W3);
    a[9]  = cmulf(a[9],  W2);
    a[10] = INV ? make_float2(-a[10].y, a[10].x) : make_float2(a[10].y, -a[10].x);
    a[11] = cmulf(a[11], W6);
    a[13] = cmulf(a[13], W3);
    a[14] = cmulf(a[14], W6);
    a[15] = cmulf(a[15], W9);
    dft4<INV>(a[0],  a[1],  a[2],  a[3]);
    dft4<INV>(a[4],  a[5],  a[6],  a[7]);
    dft4<INV>(a[8],  a[9],  a[10], a[11]);
    dft4<INV>(a[12], a[13], a[14], a[15]);
}

// DIF middle stage (forward), one butterfly: same-slot in-place. w = base twiddle.
template<int SIG>
__device__ __forceinline__ void dif_bf(float2* sm, int bf, float2 w) {
    const int S = 1 << SIG;
    int s = bf & (S - 1);
    int base = ((bf >> SIG) << (SIG + 4)) | s;
    float2 a[16];
#pragma unroll
    for (int m = 0; m < 16; m++) a[m] = sm[SW(base + (m << SIG))];
    dft16<false>(a);
    float2 w2 = cmulf(w, w);
    float2 w3 = cmulf(w2, w);
    float2 w4 = cmulf(w2, w2);
    sm[SW(base)]              = a[0];
    sm[SW(base + (1 << SIG))] = cmulf(a[sigc(1)], w);
    sm[SW(base + (2 << SIG))] = cmulf(a[sigc(2)], w2);
    sm[SW(base + (3 << SIG))] = cmulf(a[sigc(3)], w3);
    float2 bg = w4;
#pragma unroll
    for (int g = 1; g < 4; g++) {
        int u0 = g << 2;
        sm[SW(base + ((u0+0) << SIG))] = cmulf(a[sigc(u0+0)], bg);
        sm[SW(base + ((u0+1) << SIG))] = cmulf(cmulf(a[sigc(u0+1)], w),  bg);
        sm[SW(base + ((u0+2) << SIG))] = cmulf(cmulf(a[sigc(u0+2)], w2), bg);
        sm[SW(base + ((u0+3) << SIG))] = cmulf(cmulf(a[sigc(u0+3)], w3), bg);
        if (g < 3) bg = cmulf(bg, w4);
    }
}

// Inverse middle stage, one butterfly: pre-twiddle conj(w)^m via cmulcf.
template<int SIG>
__device__ __forceinline__ void dit_bf(float2* sm, int bf, float2 w) {
    const int S = 1 << SIG;
    int s = bf & (S - 1);
    int base = ((bf >> SIG) << (SIG + 4)) | s;
    float2 w2 = cmulf(w, w);
    float2 w3 = cmulf(w2, w);
    float2 w4 = cmulf(w2, w2);
    float2 a[16];
    a[0] = sm[SW(base)];
    a[1] = cmulcf(sm[SW(base + (1 << SIG))], w);
    a[2] = cmulcf(sm[SW(base + (2 << SIG))], w2);
    a[3] = cmulcf(sm[SW(base + (3 << SIG))], w3);
    float2 bg = w4;
#pragma unroll
    for (int g = 1; g < 4; g++) {
        int m0 = g << 2;
        a[m0+0] = cmulcf(sm[SW(base + ((m0+0) << SIG))], bg);
        a[m0+1] = cmulcf(cmulcf(sm[SW(base + ((m0+1) << SIG))], w),  bg);
        a[m0+2] = cmulcf(cmulcf(sm[SW(base + ((m0+2) << SIG))], w2), bg);
        a[m0+3] = cmulcf(cmulcf(sm[SW(base + ((m0+3) << SIG))], w3), bg);
        if (g < 3) bg = cmulf(bg, w4);
    }
    dft16<true>(a);
#pragma unroll
    for (int u = 0; u < 16; u++) sm[SW(base + (u << SIG))] = a[sigc(u)];
}

// Stage A forward: GMEM -> regs -> smem. w = twA[bf].
__device__ __forceinline__ void stageA_fwd(float2* sm, int bf, float2 w,
                                           const float* __restrict__ xa,
                                           const float* __restrict__ xb) {
    float2 a[16];
#pragma unroll
    for (int m = 0; m < 16; m++) {
        int i = bf + (m << 10);
        a[m] = make_float2(xa[i], xb[i]);
    }
    dft16<false>(a);
    float2 w2 = cmulf(w, w);
    float2 w3 = cmulf(w2, w);
    float2 w4 = cmulf(w2, w2);
    sm[SW(bf)]             = a[0];
    sm[SW(bf + (1<<10))]   = cmulf(a[sigc(1)], w);
    sm[SW(bf + (2<<10))]   = cmulf(a[sigc(2)], w2);
    sm[SW(bf + (3<<10))]   = cmulf(a[sigc(3)], w3);
    float2 bg = w4;
#pragma unroll
    for (int g = 1; g < 4; g++) {
        int u0 = g << 2;
        sm[SW(bf + ((u0+0)<<10))] = cmulf(a[sigc(u0+0)], bg);
        sm[SW(bf + ((u0+1)<<10))] = cmulf(cmulf(a[sigc(u0+1)], w),  bg);
        sm[SW(bf + ((u0+2)<<10))] = cmulf(cmulf(a[sigc(u0+2)], w2), bg);
        sm[SW(bf + ((u0+3)<<10))] = cmulf(cmulf(a[sigc(u0+3)], w3), bg);
        if (g < 3) bg = cmulf(bg, w4);
    }
}

// Stage A inverse: smem -> regs -> GMEM. Uses conj(w) via cmulcf.
__device__ __forceinline__ void stageA_inv(const float2* sm, int bf, float2 w,
                                           float* __restrict__ ya,
                                           float* __restrict__ yb) {
    float2 w2 = cmulf(w, w);
    float2 w3 = cmulf(w2, w);
    float2 w4 = cmulf(w2, w2);
    float2 a[16];
    a[0] = sm[SW(bf)];
    a[1] = cmulcf(sm[SW(bf + (1<<10))], w);
    a[2] = cmulcf(sm[SW(bf + (2<<10))], w2);
    a[3] = cmulcf(sm[SW(bf + (3<<10))], w3);
    float2 bg = w4;
#pragma unroll
    for (int g = 1; g < 4; g++) {
        int m0 = g << 2;
        a[m0+0] = cmulcf(sm[SW(bf + ((m0+0)<<10))], bg);
        a[m0+1] = cmulcf(cmulcf(sm[SW(bf + ((m0+1)<<10))], w),  bg);
        a[m0+2] = cmulcf(cmulcf(sm[SW(bf + ((m0+2)<<10))], w2), bg);
        a[m0+3] = cmulcf(cmulcf(sm[SW(bf + ((m0+3)<<10))], w3), bg);
        if (g < 3) bg = cmulf(bg, w4);
    }
    dft16<true>(a);
#pragma unroll
    for (int u = 0; u < 16; u++) {
        float2 v = a[sigc(u)];
        int i = bf + (u << 10);
        ya[i] = v.x;
        yb[i] = v.y;
    }
}

// ---------------------------------------------------------------------------
// Register-resident middle for one 64-block, owned by a 4-lane group.
// w1 = g_twM[s] = e^{-i pi s/32}.
// ---------------------------------------------------------------------------
__device__ __forceinline__ void mid64(float2* sm, int c, int s, int q1s, float2 w1) {
    const int base = c * 64 + s;
    float2 a[16];
#pragma unroll
    for (int m = 0; m < 16; m++) a[m] = sm[SW(base + 4*m)];
    dft16<false>(a);

    // prefetch H for this block (used after the cross-lane radix-4)
    const float4* __restrict__ h4 = (const float4*)g_Hc + ((c * 64 + q1s * 16) >> 1);
    float2 h[16];
#pragma unroll
    for (int i = 0; i < 8; i++) {
        float4 v = h4[i];
        h[2*i]   = make_float2(v.x, v.y);
        h[2*i+1] = make_float2(v.z, v.w);
    }

    float2 w2 = cmulf(w1, w1);
    float2 w3 = cmulf(w2, w1);
    float2 w4 = cmulf(w2, w2);

    // stage-C output twiddle: a[sigc(u)] *= w1^u
    {
        a[sigc(1)] = cmulf(a[sigc(1)], w1);
        a[sigc(2)] = cmulf(a[sigc(2)], w2);
        a[sigc(3)] = cmulf(a[sigc(3)], w3);
        float2 bg = w4;
#pragma unroll
        for (int g = 1; g < 4; g++) {
            int u0 = g << 2;
            a[sigc(u0+0)] = cmulf(a[sigc(u0+0)], bg);
            a[sigc(u0+1)] = cmulf(cmulf(a[sigc(u0+1)], w1), bg);
            a[sigc(u0+2)] = cmulf(cmulf(a[sigc(u0+2)], w2), bg);
            a[sigc(u0+3)] = cmulf(cmulf(a[sigc(u0+3)], w3), bg);
            if (g < 3) bg = cmulf(bg, w4);
        }
    }

    // forward cross-lane radix-4 (over s), per register. Lane ends with q1 = bitrev2(s).
#pragma unroll
    for (int r = 0; r < 16; r++) {
        float2 v = a[r];
        float2 tt = f2shfl_xor(v, 2);
        float2 u;
        if (s & 2) {
            u = f2sub(tt, v);
            if (s & 1) u = make_float2(u.y, -u.x);   // * (-i)
        } else {
            u = f2add(v, tt);
        }
        float2 t2 = f2shfl_xor(u, 1);
        a[r] = (s & 1) ? f2sub(t2, u) : f2add(u, t2);
    }

    // pointwise: new a[u] = h[u] * old a[sigc(u)]  (sigc is an involution)
    {
        a[0]  = cmulf(h[0],  a[0]);
        a[5]  = cmulf(h[5],  a[5]);
        a[10] = cmulf(h[10], a[10]);
        a[15] = cmulf(h[15], a[15]);
#pragma unroll
        for (int p = 0; p < 6; p++) {
            const int U[6] = {1, 2, 3, 6, 7, 11};
            int u = U[p], v = sigc(u);
            float2 tmp = a[u];
            a[u] = cmulf(h[u], a[v]);
            a[v] = cmulf(h[v], tmp);
        }
    }

    // inverse cross-lane radix-4, per register. Lane ends with time-role s.
#pragma unroll
    for (int r = 0; r < 16; r++) {
        float2 v = a[r];
        float2 tt = f2shfl_xor(v, 1);
        float2 u = (s & 1) ? f2sub(tt, v) : f2add(v, tt);
        if ((s & 3) == 3) u = make_float2(-u.y, u.x);   // * (+i)
        float2 t2 = f2shfl_xor(u, 2);
        a[r] = (s & 2) ? f2sub(t2, u) : f2add(u, t2);
    }

    // conj stage-C twiddle: a[u] *= conj(w1)^u  (natural q0 order)
    {
        a[1] = cmulcf(a[1], w1);
        a[2] = cmulcf(a[2], w2);
        a[3] = cmulcf(a[3], w3);
        float2 bg = w4;
#pragma unroll
        for (int g = 1; g < 4; g++) {
            int m0 = g << 2;
            a[m0+0] = cmulcf(a[m0+0], bg);
            a[m0+1] = cmulcf(cmulcf(a[m0+1], w1), bg);
            a[m0+2] = cmulcf(cmulcf(a[m0+2], w2), bg);
            a[m0+3] = cmulcf(cmulcf(a[m0+3], w3), bg);
            if (g < 3) bg = cmulf(bg, w4);
        }
    }
    dft16<true>(a);
#pragma unroll
    for (int m = 0; m < 16; m++) sm[SW(base + 4*m)] = a[sigc(m)];
}

// ---------------------------------------------------------------------------
// Main kernel: 4 barriers total, zero sincos.
// ---------------------------------------------------------------------------
__global__ __launch_bounds__(THREADS, 1)
void k_fftconv(const float* __restrict__ x, float* __restrict__ y) {
    extern __shared__ float2 sm[];
    const int t = threadIdx.x;
    const int lane = t & 31;
    const int s = lane & 3;
    const int q1s = ((s & 1) << 1) | (s >> 1);
    const int cbase = (t >> 5) * 8 + (lane >> 2);   // warp*8 + group
    const size_t row = (size_t)blockIdx.x * 2;
    const float* __restrict__ xa = x + row * L;
    const float* __restrict__ xb = xa + L;

    // base twiddles from tables (latency covered by x loads)
    const float2 wA1 = g_twA[t];
    const float2 wA2 = g_twA[t + 512];
    const float2 wB  = g_twB[t & 63];
    const float2 wM  = g_twM[s];

    stageA_fwd(sm, t,       wA1, xa, xb);
    stageA_fwd(sm, t + 512, wA2, xa, xb);
    __syncthreads();

    dif_bf<6>(sm, t,       wB);
    dif_bf<6>(sm, t + 512, wB);
    __syncthreads();

    mid64(sm, cbase,       s, q1s, wM);
    mid64(sm, cbase + 128, s, q1s, wM);
    __syncthreads();

    dit_bf<6>(sm, t,       wB);
    dit_bf<6>(sm, t + 512, wB);
    __syncthreads();

    float* __restrict__ ya = y + row * L;
    float* __restrict__ yb = ya + L;
    stageA_inv(sm, t,       wA1, ya, yb);
    stageA_inv(sm, t + 512, wA2, ya, yb);
}

// ---------------------------------------------------------------------------
extern "C" void kernel_launch(void* const* d_in, const int* in_sizes, int n_in,
                              void* d_out, int out_size) {
    const float* x  = (const float*)d_in[0];
    const float* Lr = (const float*)d_in[1];
    const float* Li = (const float*)d_in[2];
    const float* wr = (const float*)d_in[3];
    const float* wi = (const float*)d_in[4];
    const float* dt = (const float*)d_in[5];
    float* y = (float*)d_out;

    cudaFuncSetAttribute(k_fftconv, cudaFuncAttributeMaxDynamicSharedMemorySize,
                         L * sizeof(float2));

    k_hc<<<(L / 2 + 1 + 255) / 256, 256>>>(Lr, Li, wr, wi, dt);
    k_fftconv<<<(8 * 256) / 2, THREADS, L * sizeof(float2)>>>(x, y);
}